// round 1
// baseline (speedup 1.0000x reference)
#include <cuda_runtime.h>
#include <cfloat>
#include <cstddef>

#define NPTS 2048
#define BATCH 4
#define KNN 20

// ---------------- scratch (device globals; no allocation allowed) ----------
__device__ float g_x0[BATCH * 3 * NPTS];
__device__ float g_x1[BATCH * 64 * NPTS];
__device__ float g_x2[BATCH * 64 * NPTS];
__device__ float g_x3[BATCH * 128 * NPTS];
__device__ float g_x4[BATCH * 256 * NPTS];
__device__ float g_xx[BATCH * NPTS];
__device__ float g_D[(size_t)BATCH * NPTS * NPTS];       // 64 MB, reused per layer
__device__ int   g_knn[BATCH * NPTS * KNN];
__device__ float g_Y[BATCH * NPTS * 256];                // n-major, stride 256
__device__ float g_Z[BATCH * NPTS * 256];
__device__ float g_h5[(size_t)BATCH * NPTS * 1024];      // 32 MB
__device__ float g_f[BATCH * 2048];
__device__ float g_fc1[BATCH * 512];

__device__ __forceinline__ float lrelu(float v) { return v > 0.f ? v : 0.2f * v; }
#define BN_RSQ 0.99999500003749968750f  /* rsqrt(1+1e-5) */

// ---------------- transpose points (B,N,3) -> (B,3,N) ----------------------
__global__ void k_transpose(const float* __restrict__ pts) {
    int i = blockIdx.x * blockDim.x + threadIdx.x;
    if (i < BATCH * NPTS) {
        int b = i / NPTS, n = i % NPTS;
        #pragma unroll
        for (int c = 0; c < 3; c++)
            g_x0[(b * 3 + c) * NPTS + n] = pts[(b * NPTS + n) * 3 + c];
    }
}

// ---------------- row norms ------------------------------------------------
__global__ void k_xx(const float* __restrict__ feat, int C) {
    int i = blockIdx.x * blockDim.x + threadIdx.x;
    if (i < BATCH * NPTS) {
        int b = i / NPTS, n = i % NPTS;
        const float* f = feat + (size_t)b * C * NPTS + n;
        float s = 0.f;
        for (int c = 0; c < C; c++) { float v = f[(size_t)c * NPTS]; s = fmaf(v, v, s); }
        g_xx[i] = s;
    }
}

// ---------------- distance GEMM: D = 2 X^T X - xx_i - xx_j -----------------
// grid (N/64, N/64, B), 256 threads, 64x64 tile, 4x4 per thread
__global__ void k_dist(const float* __restrict__ feat, int C) {
    __shared__ float As[16][64];
    __shared__ float Bs[16][64];
    int b = blockIdx.z;
    int i0 = blockIdx.y * 64, j0 = blockIdx.x * 64;
    const float* fb = feat + (size_t)b * C * NPTS;
    int tx = threadIdx.x & 15, ty = threadIdx.x >> 4;
    float acc[4][4] = {};
    for (int c0 = 0; c0 < C; c0 += 16) {
        for (int e = threadIdx.x; e < 1024; e += 256) {
            int kk = e >> 6, ii = e & 63;
            int c = c0 + kk;
            float va = 0.f, vb = 0.f;
            if (c < C) {
                va = fb[(size_t)c * NPTS + i0 + ii];
                vb = fb[(size_t)c * NPTS + j0 + ii];
            }
            As[kk][ii] = va;
            Bs[kk][ii] = vb;
        }
        __syncthreads();
        #pragma unroll
        for (int kk = 0; kk < 16; kk++) {
            float4 a4 = *(const float4*)&As[kk][ty * 4];
            float4 b4 = *(const float4*)&Bs[kk][tx * 4];
            float av[4] = {a4.x, a4.y, a4.z, a4.w};
            float bv[4] = {b4.x, b4.y, b4.z, b4.w};
            #pragma unroll
            for (int r = 0; r < 4; r++)
                #pragma unroll
                for (int s = 0; s < 4; s++)
                    acc[r][s] = fmaf(av[r], bv[s], acc[r][s]);
        }
        __syncthreads();
    }
    float xj[4];
    #pragma unroll
    for (int s = 0; s < 4; s++) xj[s] = g_xx[b * NPTS + j0 + tx * 4 + s];
    #pragma unroll
    for (int r = 0; r < 4; r++) {
        int i = i0 + ty * 4 + r;
        float xi = g_xx[b * NPTS + i];
        float4 o;
        o.x = 2.f * acc[r][0] - xi - xj[0];
        o.y = 2.f * acc[r][1] - xi - xj[1];
        o.z = 2.f * acc[r][2] - xi - xj[2];
        o.w = 2.f * acc[r][3] - xi - xj[3];
        *(float4*)&g_D[((size_t)b * NPTS + i) * NPTS + j0 + tx * 4] = o;
    }
}

// ---------------- top-K (K=20, largest, ties -> lower index) ---------------
// grid (N, B), 256 threads
__global__ void k_topk() {
    __shared__ float dv[NPTS];
    __shared__ float rv[256];
    __shared__ int   ri[256];
    int b = blockIdx.y, row = blockIdx.x;
    const float* drow = g_D + ((size_t)b * NPTS + row) * NPTS;
    for (int j = threadIdx.x; j < NPTS; j += 256) dv[j] = drow[j];
    __syncthreads();
    for (int it = 0; it < KNN; it++) {
        float best = -FLT_MAX; int bi = NPTS;
        for (int j = threadIdx.x; j < NPTS; j += 256) {
            float v = dv[j];
            if (v > best) { best = v; bi = j; }   // ties keep earlier (smaller) j
        }
        rv[threadIdx.x] = best; ri[threadIdx.x] = bi;
        __syncthreads();
        for (int s = 128; s > 0; s >>= 1) {
            if (threadIdx.x < s) {
                float v2 = rv[threadIdx.x + s]; int i2 = ri[threadIdx.x + s];
                if (v2 > rv[threadIdx.x] ||
                    (v2 == rv[threadIdx.x] && i2 < ri[threadIdx.x])) {
                    rv[threadIdx.x] = v2; ri[threadIdx.x] = i2;
                }
            }
            __syncthreads();
        }
        if (threadIdx.x == 0) {
            g_knn[((size_t)b * NPTS + row) * KNN + it] = ri[0];
            dv[ri[0]] = -FLT_MAX;
        }
        __syncthreads();
    }
}

// ---------------- Y = W2 X, Z = (W1-W2) X ; stored n-major stride 256 ------
// grid (N/64, Cout/64, B), 256 threads
__global__ void k_yz(const float* __restrict__ feat, const float* __restrict__ W,
                     int C, int Cout) {
    __shared__ float As[16][64];
    __shared__ float B1[16][64];
    __shared__ float B2[16][64];
    int b = blockIdx.z;
    int n0 = blockIdx.x * 64, o0 = blockIdx.y * 64;
    const float* fb = feat + (size_t)b * C * NPTS;
    int tx = threadIdx.x & 15, ty = threadIdx.x >> 4;
    float aU[4][4] = {}, aY[4][4] = {};
    for (int c0 = 0; c0 < C; c0 += 16) {
        for (int e = threadIdx.x; e < 1024; e += 256) {
            int kk = e >> 6, nn = e & 63;
            int c = c0 + kk;
            As[kk][nn] = (c < C) ? fb[(size_t)c * NPTS + n0 + nn] : 0.f;
        }
        for (int e = threadIdx.x; e < 1024; e += 256) {
            int kk = e & 15, oo = e >> 4;
            int c = c0 + kk;
            float w1 = 0.f, w2 = 0.f;
            if (c < C) {
                const float* wr = W + (size_t)(o0 + oo) * (2 * C);
                w1 = wr[c]; w2 = wr[C + c];
            }
            B1[kk][oo] = w1; B2[kk][oo] = w2;
        }
        __syncthreads();
        #pragma unroll
        for (int kk = 0; kk < 16; kk++) {
            float4 a4 = *(const float4*)&As[kk][ty * 4];
            float4 b14 = *(const float4*)&B1[kk][tx * 4];
            float4 b24 = *(const float4*)&B2[kk][tx * 4];
            float av[4] = {a4.x, a4.y, a4.z, a4.w};
            float b1v[4] = {b14.x, b14.y, b14.z, b14.w};
            float b2v[4] = {b24.x, b24.y, b24.z, b24.w};
            #pragma unroll
            for (int r = 0; r < 4; r++)
                #pragma unroll
                for (int s = 0; s < 4; s++) {
                    aU[r][s] = fmaf(av[r], b1v[s], aU[r][s]);
                    aY[r][s] = fmaf(av[r], b2v[s], aY[r][s]);
                }
        }
        __syncthreads();
    }
    #pragma unroll
    for (int r = 0; r < 4; r++) {
        int n = n0 + ty * 4 + r;
        size_t base = ((size_t)b * NPTS + n) * 256 + o0 + tx * 4;
        float4 y, z;
        y.x = aY[r][0]; y.y = aY[r][1]; y.z = aY[r][2]; y.w = aY[r][3];
        z.x = aU[r][0] - y.x; z.y = aU[r][1] - y.y;
        z.z = aU[r][2] - y.z; z.w = aU[r][3] - y.w;
        *(float4*)&g_Y[base] = y;
        *(float4*)&g_Z[base] = z;
    }
}

// ---------------- gather-max + BN + lrelu -> feat_out (B,Cout,N) -----------
// grid (N/32, B), blockDim = Cout
__global__ void k_gather(float* __restrict__ out, const float* __restrict__ gam,
                         const float* __restrict__ bet, int Cout) {
    __shared__ int   sidx[32 * KNN];
    __shared__ float sout[256 * 33];
    int b = blockIdx.y, n0 = blockIdx.x * 32;
    for (int e = threadIdx.x; e < 32 * KNN; e += blockDim.x)
        sidx[e] = g_knn[((size_t)b * NPTS + n0) * KNN + e];
    __syncthreads();
    int o = threadIdx.x;
    float sc = gam[o] * BN_RSQ, bi = bet[o];
    const float* Yb = g_Y + (size_t)b * NPTS * 256;
    const float* Zb = g_Z + (size_t)b * NPTS * 256;
    for (int nn = 0; nn < 32; nn++) {
        float m = -FLT_MAX;
        #pragma unroll
        for (int k = 0; k < KNN; k++) {
            int j = sidx[nn * KNN + k];
            m = fmaxf(m, Yb[(size_t)j * 256 + o]);
        }
        float v = Zb[(size_t)(n0 + nn) * 256 + o] + m;
        v = lrelu(fmaf(v, sc, bi));
        sout[o * 33 + nn] = v;
    }
    __syncthreads();
    float* ob = out + (size_t)b * Cout * NPTS;
    for (int e = threadIdx.x; e < Cout * 32; e += blockDim.x) {
        int oo = e >> 5, nn = e & 31;
        ob[(size_t)oo * NPTS + n0 + nn] = sout[oo * 33 + nn];
    }
}

// ---------------- conv5 (512->1024) + BN + lrelu -> g_h5 (n-major) ---------
// grid (N/64, 1024/64, B), 256 threads
__global__ void k_conv5(const float* __restrict__ W5, const float* __restrict__ gam,
                        const float* __restrict__ bet) {
    __shared__ float As[16][64];
    __shared__ float Bs[16][64];
    int b = blockIdx.z;
    int n0 = blockIdx.x * 64, o0 = blockIdx.y * 64;
    int tx = threadIdx.x & 15, ty = threadIdx.x >> 4;
    float acc[4][4] = {};
    for (int c0 = 0; c0 < 512; c0 += 16) {
        const float* src; int cb;
        if (c0 < 64)       { src = g_x1 + (size_t)b * 64 * NPTS;  cb = c0; }
        else if (c0 < 128) { src = g_x2 + (size_t)b * 64 * NPTS;  cb = c0 - 64; }
        else if (c0 < 256) { src = g_x3 + (size_t)b * 128 * NPTS; cb = c0 - 128; }
        else               { src = g_x4 + (size_t)b * 256 * NPTS; cb = c0 - 256; }
        for (int e = threadIdx.x; e < 1024; e += 256) {
            int kk = e >> 6, nn = e & 63;
            As[kk][nn] = src[(size_t)(cb + kk) * NPTS + n0 + nn];
        }
        for (int e = threadIdx.x; e < 1024; e += 256) {
            int kk = e & 15, oo = e >> 4;
            Bs[kk][oo] = W5[(size_t)(o0 + oo) * 512 + c0 + kk];
        }
        __syncthreads();
        #pragma unroll
        for (int kk = 0; kk < 16; kk++) {
            float4 a4 = *(const float4*)&As[kk][ty * 4];
            float4 b4 = *(const float4*)&Bs[kk][tx * 4];
            float av[4] = {a4.x, a4.y, a4.z, a4.w};
            float bv[4] = {b4.x, b4.y, b4.z, b4.w};
            #pragma unroll
            for (int r = 0; r < 4; r++)
                #pragma unroll
                for (int s = 0; s < 4; s++)
                    acc[r][s] = fmaf(av[r], bv[s], acc[r][s]);
        }
        __syncthreads();
    }
    float sc[4], bi[4];
    #pragma unroll
    for (int s = 0; s < 4; s++) {
        int o = o0 + tx * 4 + s;
        sc[s] = gam[o] * BN_RSQ; bi[s] = bet[o];
    }
    #pragma unroll
    for (int r = 0; r < 4; r++) {
        int n = n0 + ty * 4 + r;
        float4 o;
        o.x = lrelu(fmaf(acc[r][0], sc[0], bi[0]));
        o.y = lrelu(fmaf(acc[r][1], sc[1], bi[1]));
        o.z = lrelu(fmaf(acc[r][2], sc[2], bi[2]));
        o.w = lrelu(fmaf(acc[r][3], sc[3], bi[3]));
        *(float4*)&g_h5[((size_t)b * NPTS + n) * 1024 + o0 + tx * 4] = o;
    }
}

// ---------------- global max + mean pool -> g_f (B, 2048) ------------------
// grid (1024/256, B), 256 threads
__global__ void k_pool() {
    int b = blockIdx.y;
    int o = blockIdx.x * 256 + threadIdx.x;
    const float* h = g_h5 + (size_t)b * NPTS * 1024;
    float mx = -FLT_MAX, sm = 0.f;
    #pragma unroll 8
    for (int n = 0; n < NPTS; n++) {
        float v = h[(size_t)n * 1024 + o];
        mx = fmaxf(mx, v);
        sm += v;
    }
    g_f[b * 2048 + o] = mx;
    g_f[b * 2048 + 1024 + o] = sm * (1.0f / NPTS);
}

// ---------------- fc1: 2048->512, BN + lrelu -------------------------------
// grid (64, B), 256 threads (8 warps; warp -> one output)
__global__ void k_fc1(const float* __restrict__ fw, const float* __restrict__ fb,
                      const float* __restrict__ gam, const float* __restrict__ bet) {
    int b = blockIdx.y;
    int w = threadIdx.x >> 5, lane = threadIdx.x & 31;
    int o = blockIdx.x * 8 + w;
    const float* f = g_f + b * 2048;
    const float* wr = fw + (size_t)o * 2048;
    float acc = 0.f;
    for (int c = lane; c < 2048; c += 32) acc = fmaf(f[c], wr[c], acc);
    #pragma unroll
    for (int s = 16; s > 0; s >>= 1) acc += __shfl_xor_sync(0xffffffffu, acc, s);
    if (lane == 0) {
        float v = acc + fb[o];
        v = lrelu(fmaf(v, gam[o] * BN_RSQ, bet[o]));
        g_fc1[b * 512 + o] = v;
    }
}

// ---------------- fc2: 512->256, BN (no lrelu) -> d_out --------------------
// grid (32, B), 256 threads
__global__ void k_fc2(const float* __restrict__ fw, const float* __restrict__ fb,
                      const float* __restrict__ gam, const float* __restrict__ bet,
                      float* __restrict__ out) {
    int b = blockIdx.y;
    int w = threadIdx.x >> 5, lane = threadIdx.x & 31;
    int o = blockIdx.x * 8 + w;
    const float* f = g_fc1 + b * 512;
    const float* wr = fw + (size_t)o * 512;
    float acc = 0.f;
    for (int c = lane; c < 512; c += 32) acc = fmaf(f[c], wr[c], acc);
    #pragma unroll
    for (int s = 16; s > 0; s >>= 1) acc += __shfl_xor_sync(0xffffffffu, acc, s);
    if (lane == 0) {
        float v = acc + fb[o];
        out[b * 256 + o] = fmaf(v, gam[o] * BN_RSQ, bet[o]);
    }
}

// ---------------- driver ---------------------------------------------------
static void run_edge(const float* feat, int C, const float* W,
                     const float* gam, const float* bet,
                     float* out, int Cout) {
    k_xx<<<(BATCH * NPTS + 255) / 256, 256>>>(feat, C);
    k_dist<<<dim3(NPTS / 64, NPTS / 64, BATCH), 256>>>(feat, C);
    k_topk<<<dim3(NPTS, BATCH), 256>>>();
    k_yz<<<dim3(NPTS / 64, Cout / 64, BATCH), 256>>>(feat, W, C, Cout);
    k_gather<<<dim3(NPTS / 32, BATCH), Cout>>>(out, gam, bet, Cout);
}

extern "C" void kernel_launch(void* const* d_in, const int* in_sizes, int n_in,
                              void* d_out, int out_size) {
    const float* pts = (const float*)d_in[0];
    const float* w1 = (const float*)d_in[1];
    const float* g1 = (const float*)d_in[2];
    const float* b1 = (const float*)d_in[3];
    const float* w2 = (const float*)d_in[4];
    const float* g2 = (const float*)d_in[5];
    const float* b2 = (const float*)d_in[6];
    const float* w3 = (const float*)d_in[7];
    const float* g3 = (const float*)d_in[8];
    const float* b3 = (const float*)d_in[9];
    const float* w4 = (const float*)d_in[10];
    const float* g4 = (const float*)d_in[11];
    const float* b4 = (const float*)d_in[12];
    const float* w5 = (const float*)d_in[13];
    const float* g5 = (const float*)d_in[14];
    const float* b5 = (const float*)d_in[15];
    const float* fw1 = (const float*)d_in[16];
    const float* fb1 = (const float*)d_in[17];
    const float* g6 = (const float*)d_in[18];
    const float* b6 = (const float*)d_in[19];
    const float* fw2 = (const float*)d_in[20];
    const float* fb2 = (const float*)d_in[21];
    const float* g7 = (const float*)d_in[22];
    const float* b7 = (const float*)d_in[23];

    float *x0, *x1, *x2, *x3, *x4;
    cudaGetSymbolAddress((void**)&x0, g_x0);
    cudaGetSymbolAddress((void**)&x1, g_x1);
    cudaGetSymbolAddress((void**)&x2, g_x2);
    cudaGetSymbolAddress((void**)&x3, g_x3);
    cudaGetSymbolAddress((void**)&x4, g_x4);

    k_transpose<<<(BATCH * NPTS + 255) / 256, 256>>>(pts);
    run_edge(x0, 3,   w1, g1, b1, x1, 64);
    run_edge(x1, 64,  w2, g2, b2, x2, 64);
    run_edge(x2, 64,  w3, g3, b3, x3, 128);
    run_edge(x3, 128, w4, g4, b4, x4, 256);
    k_conv5<<<dim3(NPTS / 64, 1024 / 64, BATCH), 256>>>(w5, g5, b5);
    k_pool<<<dim3(1024 / 256, BATCH), 256>>>();
    k_fc1<<<dim3(512 / 8, BATCH), 256>>>(fw1, fb1, g6, b6);
    k_fc2<<<dim3(256 / 8, BATCH), 256>>>(fw2, fb2, g7, b7, (float*)d_out);
}

// round 2
// speedup vs baseline: 1.3878x; 1.3878x over previous
#include <cuda_runtime.h>
#include <cfloat>
#include <cstddef>

#define NPTS 2048
#define BATCH 4
#define KNN 20

// ---------------- scratch (device globals; no allocation allowed) ----------
__device__ float g_x0[BATCH * 3 * NPTS];
// concat feature buffer: (B, 512, N). x1 @ ch 0, x2 @ 64, x3 @ 128, x4 @ 256
__device__ float g_xcat[(size_t)BATCH * 512 * NPTS];
__device__ float g_xx[BATCH * NPTS];
__device__ float g_D[(size_t)BATCH * NPTS * NPTS];       // 64 MB, reused per layer
__device__ int   g_knn[BATCH * NPTS * KNN];
__device__ float g_Y[BATCH * NPTS * 256];                // n-major, stride 256
__device__ float g_Z[BATCH * NPTS * 256];
__device__ float g_h5[(size_t)BATCH * NPTS * 1024];      // 32 MB
__device__ float g_f[BATCH * 2048];
__device__ float g_fc1[BATCH * 512];

__device__ __forceinline__ float lrelu(float v) { return v > 0.f ? v : 0.2f * v; }
#define BN_RSQ 0.99999500003749968750f  /* rsqrt(1+1e-5) */
#define CAT_BSTR (512 * NPTS)

// ---------------- transpose points (B,N,3) -> (B,3,N) ----------------------
__global__ void k_transpose(const float* __restrict__ pts) {
    int i = blockIdx.x * blockDim.x + threadIdx.x;
    if (i < BATCH * NPTS) {
        int b = i / NPTS, n = i % NPTS;
        #pragma unroll
        for (int c = 0; c < 3; c++)
            g_x0[(b * 3 + c) * NPTS + n] = pts[(b * NPTS + n) * 3 + c];
    }
}

// ---------------- row norms ------------------------------------------------
__global__ void k_xx(const float* __restrict__ feat, int C, int bstr) {
    int i = blockIdx.x * blockDim.x + threadIdx.x;
    if (i < BATCH * NPTS) {
        int b = i / NPTS, n = i % NPTS;
        const float* f = feat + (size_t)b * bstr + n;
        float s = 0.f;
        for (int c = 0; c < C; c++) { float v = f[(size_t)c * NPTS]; s = fmaf(v, v, s); }
        g_xx[i] = s;
    }
}

// ---------------- distance GEMM: D = 2 X^T X - xx_i - xx_j -----------------
// 128x128 tile, 8x8 per thread, K-step 8. grid (N/128, N/128, B), 256 thr.
__global__ void k_dist(const float* __restrict__ feat, int C, int bstr) {
    __shared__ float As[8][128];
    __shared__ float Bs[8][128];
    int b = blockIdx.z;
    int i0 = blockIdx.y * 128, j0 = blockIdx.x * 128;
    const float* fb = feat + (size_t)b * bstr;
    int tx = threadIdx.x & 15, ty = threadIdx.x >> 4;
    int lr = threadIdx.x & 31, lc = threadIdx.x >> 5;   // load: col-group, k-row
    float acc[8][8] = {};
    for (int c0 = 0; c0 < C; c0 += 8) {
        int c = c0 + lc;
        float4 av = {0.f, 0.f, 0.f, 0.f}, bv = {0.f, 0.f, 0.f, 0.f};
        if (c < C) {
            av = *(const float4*)&fb[(size_t)c * NPTS + i0 + lr * 4];
            bv = *(const float4*)&fb[(size_t)c * NPTS + j0 + lr * 4];
        }
        *(float4*)&As[lc][lr * 4] = av;
        *(float4*)&Bs[lc][lr * 4] = bv;
        __syncthreads();
        #pragma unroll
        for (int kk = 0; kk < 8; kk++) {
            float a[8], bb[8];
            *(float4*)&a[0] = *(const float4*)&As[kk][ty * 8];
            *(float4*)&a[4] = *(const float4*)&As[kk][ty * 8 + 4];
            *(float4*)&bb[0] = *(const float4*)&Bs[kk][tx * 8];
            *(float4*)&bb[4] = *(const float4*)&Bs[kk][tx * 8 + 4];
            #pragma unroll
            for (int r = 0; r < 8; r++)
                #pragma unroll
                for (int s = 0; s < 8; s++)
                    acc[r][s] = fmaf(a[r], bb[s], acc[r][s]);
        }
        __syncthreads();
    }
    float xj[8];
    #pragma unroll
    for (int s = 0; s < 8; s++) xj[s] = g_xx[b * NPTS + j0 + tx * 8 + s];
    #pragma unroll
    for (int r = 0; r < 8; r++) {
        int i = i0 + ty * 8 + r;
        float xi = g_xx[b * NPTS + i];
        float o[8];
        #pragma unroll
        for (int s = 0; s < 8; s++) o[s] = 2.f * acc[r][s] - xi - xj[s];
        float* dst = &g_D[((size_t)b * NPTS + i) * NPTS + j0 + tx * 8];
        *(float4*)&dst[0] = *(float4*)&o[0];
        *(float4*)&dst[4] = *(float4*)&o[4];
    }
}

// ---------------- top-K (K=20, largest, ties -> lower index) ---------------
// warp per row; per-lane sorted register top-20, warp-shfl merge.
// grid (B*N/8), 256 threads
__global__ void k_topk() {
    int warp = threadIdx.x >> 5, lane = threadIdx.x & 31;
    int row = blockIdx.x * 8 + warp;          // row = b*N + n
    const float* drow = g_D + (size_t)row * NPTS;

    float arr[KNN];
    int   ai[KNN];
    #pragma unroll
    for (int q = 0; q < KNN; q++) { arr[q] = -FLT_MAX; ai[q] = 0x7FFFFFFF; }

    // scan: 16 float4 loads per lane, ascending j within lane
    #pragma unroll 4
    for (int t = 0; t < NPTS / 128; t++) {
        int jb = t * 128 + lane * 4;
        float4 v4 = *(const float4*)&drow[jb];
        float vv[4] = {v4.x, v4.y, v4.z, v4.w};
        #pragma unroll
        for (int m = 0; m < 4; m++) {
            float v = vv[m];
            if (v > arr[0]) {                 // strict: tie keeps earlier index
                arr[0] = v; ai[0] = jb + m;
                #pragma unroll
                for (int q = 0; q < KNN - 1; q++) {
                    if (arr[q + 1] < arr[q]) {
                        float tv = arr[q]; arr[q] = arr[q + 1]; arr[q + 1] = tv;
                        int ti = ai[q]; ai[q] = ai[q + 1]; ai[q + 1] = ti;
                    }
                }
            }
        }
    }

    // merge: 20 pops, warp argmax (value desc, index asc on ties)
    #pragma unroll 1
    for (int k = 0; k < KNN; k++) {
        float cv = arr[KNN - 1];
        int   ci = ai[KNN - 1];
        float wv = cv; int wi = ci;
        #pragma unroll
        for (int s = 16; s > 0; s >>= 1) {
            float ov = __shfl_xor_sync(0xffffffffu, wv, s);
            int   oi = __shfl_xor_sync(0xffffffffu, wi, s);
            if (ov > wv || (ov == wv && oi < wi)) { wv = ov; wi = oi; }
        }
        if (lane == 0) g_knn[(size_t)row * KNN + k] = wi;
        if (ci == wi) {                        // this lane's max was consumed
            #pragma unroll
            for (int q = KNN - 1; q > 0; q--) { arr[q] = arr[q - 1]; ai[q] = ai[q - 1]; }
            arr[0] = -FLT_MAX; ai[0] = 0x7FFFFFFF;
        }
    }
}

// ---------------- Y = W2 X, Z = (W1-W2) X ; stored n-major stride 256 ------
// grid (N/64, Cout/64, B), 256 threads
__global__ void k_yz(const float* __restrict__ feat, const float* __restrict__ W,
                     int C, int Cout, int bstr) {
    __shared__ float As[16][64];
    __shared__ float B1[16][64];
    __shared__ float B2[16][64];
    int b = blockIdx.z;
    int n0 = blockIdx.x * 64, o0 = blockIdx.y * 64;
    const float* fb = feat + (size_t)b * bstr;
    int tx = threadIdx.x & 15, ty = threadIdx.x >> 4;
    float aU[4][4] = {}, aY[4][4] = {};
    for (int c0 = 0; c0 < C; c0 += 16) {
        for (int e = threadIdx.x; e < 1024; e += 256) {
            int kk = e >> 6, nn = e & 63;
            int c = c0 + kk;
            As[kk][nn] = (c < C) ? fb[(size_t)c * NPTS + n0 + nn] : 0.f;
        }
        for (int e = threadIdx.x; e < 1024; e += 256) {
            int kk = e & 15, oo = e >> 4;
            int c = c0 + kk;
            float w1 = 0.f, w2 = 0.f;
            if (c < C) {
                const float* wr = W + (size_t)(o0 + oo) * (2 * C);
                w1 = wr[c]; w2 = wr[C + c];
            }
            B1[kk][oo] = w1; B2[kk][oo] = w2;
        }
        __syncthreads();
        #pragma unroll
        for (int kk = 0; kk < 16; kk++) {
            float4 a4 = *(const float4*)&As[kk][ty * 4];
            float4 b14 = *(const float4*)&B1[kk][tx * 4];
            float4 b24 = *(const float4*)&B2[kk][tx * 4];
            float av[4] = {a4.x, a4.y, a4.z, a4.w};
            float b1v[4] = {b14.x, b14.y, b14.z, b14.w};
            float b2v[4] = {b24.x, b24.y, b24.z, b24.w};
            #pragma unroll
            for (int r = 0; r < 4; r++)
                #pragma unroll
                for (int s = 0; s < 4; s++) {
                    aU[r][s] = fmaf(av[r], b1v[s], aU[r][s]);
                    aY[r][s] = fmaf(av[r], b2v[s], aY[r][s]);
                }
        }
        __syncthreads();
    }
    #pragma unroll
    for (int r = 0; r < 4; r++) {
        int n = n0 + ty * 4 + r;
        size_t base = ((size_t)b * NPTS + n) * 256 + o0 + tx * 4;
        float4 y, z;
        y.x = aY[r][0]; y.y = aY[r][1]; y.z = aY[r][2]; y.w = aY[r][3];
        z.x = aU[r][0] - y.x; z.y = aU[r][1] - y.y;
        z.z = aU[r][2] - y.z; z.w = aU[r][3] - y.w;
        *(float4*)&g_Y[base] = y;
        *(float4*)&g_Z[base] = z;
    }
}

// ---------------- gather-max + BN + lrelu -> out slice of g_xcat -----------
// grid (N/32, B), blockDim = Cout
__global__ void k_gather(float* __restrict__ out, const float* __restrict__ gam,
                         const float* __restrict__ bet, int Cout, int bstr) {
    __shared__ int   sidx[32 * KNN];
    __shared__ float sout[256 * 33];
    int b = blockIdx.y, n0 = blockIdx.x * 32;
    for (int e = threadIdx.x; e < 32 * KNN; e += blockDim.x)
        sidx[e] = g_knn[((size_t)b * NPTS + n0) * KNN + e];
    __syncthreads();
    int o = threadIdx.x;
    float sc = gam[o] * BN_RSQ, bi = bet[o];
    const float* Yb = g_Y + (size_t)b * NPTS * 256;
    const float* Zb = g_Z + (size_t)b * NPTS * 256;
    for (int nn = 0; nn < 32; nn++) {
        float m = -FLT_MAX;
        #pragma unroll
        for (int k = 0; k < KNN; k++) {
            int j = sidx[nn * KNN + k];
            m = fmaxf(m, Yb[(size_t)j * 256 + o]);
        }
        float v = Zb[(size_t)(n0 + nn) * 256 + o] + m;
        v = lrelu(fmaf(v, sc, bi));
        sout[o * 33 + nn] = v;
    }
    __syncthreads();
    float* ob = out + (size_t)b * bstr;
    for (int e = threadIdx.x; e < Cout * 32; e += blockDim.x) {
        int oo = e >> 5, nn = e & 31;
        ob[(size_t)oo * NPTS + n0 + nn] = sout[oo * 33 + nn];
    }
}

// ---------------- conv5 (512->1024) + BN + lrelu -> g_h5 (n-major) ---------
// 128x128 tile, 8x8/thread. grid (N/128, 1024/128, B), 256 threads
__global__ void k_conv5(const float* __restrict__ W5, const float* __restrict__ gam,
                        const float* __restrict__ bet) {
    __shared__ float As[8][128];
    __shared__ float Bs[8][128];
    int b = blockIdx.z;
    int n0 = blockIdx.x * 128, o0 = blockIdx.y * 128;
    int tx = threadIdx.x & 15, ty = threadIdx.x >> 4;
    int lr = threadIdx.x & 31, lc = threadIdx.x >> 5;
    int wo = threadIdx.x >> 1, wk = (threadIdx.x & 1) * 4;   // weight-load mapping
    const float* xb = g_xcat + (size_t)b * CAT_BSTR;
    float acc[8][8] = {};
    for (int c0 = 0; c0 < 512; c0 += 8) {
        float4 av = *(const float4*)&xb[(size_t)(c0 + lc) * NPTS + n0 + lr * 4];
        float4 wv = *(const float4*)&W5[(size_t)(o0 + wo) * 512 + c0 + wk];
        *(float4*)&As[lc][lr * 4] = av;
        Bs[wk + 0][wo] = wv.x;
        Bs[wk + 1][wo] = wv.y;
        Bs[wk + 2][wo] = wv.z;
        Bs[wk + 3][wo] = wv.w;
        __syncthreads();
        #pragma unroll
        for (int kk = 0; kk < 8; kk++) {
            float a[8], bb[8];
            *(float4*)&a[0] = *(const float4*)&As[kk][ty * 8];
            *(float4*)&a[4] = *(const float4*)&As[kk][ty * 8 + 4];
            *(float4*)&bb[0] = *(const float4*)&Bs[kk][tx * 8];
            *(float4*)&bb[4] = *(const float4*)&Bs[kk][tx * 8 + 4];
            #pragma unroll
            for (int r = 0; r < 8; r++)
                #pragma unroll
                for (int s = 0; s < 8; s++)
                    acc[r][s] = fmaf(a[r], bb[s], acc[r][s]);
        }
        __syncthreads();
    }
    float sc[8], bi[8];
    #pragma unroll
    for (int s = 0; s < 8; s++) {
        int o = o0 + tx * 8 + s;
        sc[s] = gam[o] * BN_RSQ; bi[s] = bet[o];
    }
    #pragma unroll
    for (int r = 0; r < 8; r++) {
        int n = n0 + ty * 8 + r;
        float o[8];
        #pragma unroll
        for (int s = 0; s < 8; s++) o[s] = lrelu(fmaf(acc[r][s], sc[s], bi[s]));
        float* dst = &g_h5[((size_t)b * NPTS + n) * 1024 + o0 + tx * 8];
        *(float4*)&dst[0] = *(float4*)&o[0];
        *(float4*)&dst[4] = *(float4*)&o[4];
    }
}

// ---------------- global max + mean pool -> g_f (B, 2048) ------------------
__global__ void k_pool() {
    int b = blockIdx.y;
    int o = blockIdx.x * 256 + threadIdx.x;
    const float* h = g_h5 + (size_t)b * NPTS * 1024;
    float mx = -FLT_MAX, sm = 0.f;
    #pragma unroll 8
    for (int n = 0; n < NPTS; n++) {
        float v = h[(size_t)n * 1024 + o];
        mx = fmaxf(mx, v);
        sm += v;
    }
    g_f[b * 2048 + o] = mx;
    g_f[b * 2048 + 1024 + o] = sm * (1.0f / NPTS);
}

// ---------------- fc1: 2048->512, BN + lrelu -------------------------------
__global__ void k_fc1(const float* __restrict__ fw, const float* __restrict__ fb,
                      const float* __restrict__ gam, const float* __restrict__ bet) {
    int b = blockIdx.y;
    int w = threadIdx.x >> 5, lane = threadIdx.x & 31;
    int o = blockIdx.x * 8 + w;
    const float* f = g_f + b * 2048;
    const float* wr = fw + (size_t)o * 2048;
    float acc = 0.f;
    for (int c = lane; c < 2048; c += 32) acc = fmaf(f[c], wr[c], acc);
    #pragma unroll
    for (int s = 16; s > 0; s >>= 1) acc += __shfl_xor_sync(0xffffffffu, acc, s);
    if (lane == 0) {
        float v = acc + fb[o];
        v = lrelu(fmaf(v, gam[o] * BN_RSQ, bet[o]));
        g_fc1[b * 512 + o] = v;
    }
}

// ---------------- fc2: 512->256, BN (no lrelu) -> d_out --------------------
__global__ void k_fc2(const float* __restrict__ fw, const float* __restrict__ fb,
                      const float* __restrict__ gam, const float* __restrict__ bet,
                      float* __restrict__ out) {
    int b = blockIdx.y;
    int w = threadIdx.x >> 5, lane = threadIdx.x & 31;
    int o = blockIdx.x * 8 + w;
    const float* f = g_fc1 + b * 512;
    const float* wr = fw + (size_t)o * 512;
    float acc = 0.f;
    for (int c = lane; c < 512; c += 32) acc = fmaf(f[c], wr[c], acc);
    #pragma unroll
    for (int s = 16; s > 0; s >>= 1) acc += __shfl_xor_sync(0xffffffffu, acc, s);
    if (lane == 0) {
        float v = acc + fb[o];
        out[b * 256 + o] = fmaf(v, gam[o] * BN_RSQ, bet[o]);
    }
}

// ---------------- driver ---------------------------------------------------
static void run_edge(const float* feat, int C, int bstr, const float* W,
                     const float* gam, const float* bet,
                     float* out, int Cout) {
    k_xx<<<(BATCH * NPTS + 255) / 256, 256>>>(feat, C, bstr);
    k_dist<<<dim3(NPTS / 128, NPTS / 128, BATCH), 256>>>(feat, C, bstr);
    k_topk<<<BATCH * NPTS / 8, 256>>>();
    k_yz<<<dim3(NPTS / 64, Cout / 64, BATCH), 256>>>(feat, W, C, Cout, bstr);
    k_gather<<<dim3(NPTS / 32, BATCH), Cout>>>(out, gam, bet, Cout, CAT_BSTR);
}

extern "C" void kernel_launch(void* const* d_in, const int* in_sizes, int n_in,
                              void* d_out, int out_size) {
    const float* pts = (const float*)d_in[0];
    const float* w1 = (const float*)d_in[1];
    const float* g1 = (const float*)d_in[2];
    const float* b1 = (const float*)d_in[3];
    const float* w2 = (const float*)d_in[4];
    const float* g2 = (const float*)d_in[5];
    const float* b2 = (const float*)d_in[6];
    const float* w3 = (const float*)d_in[7];
    const float* g3 = (const float*)d_in[8];
    const float* b3 = (const float*)d_in[9];
    const float* w4 = (const float*)d_in[10];
    const float* g4 = (const float*)d_in[11];
    const float* b4 = (const float*)d_in[12];
    const float* w5 = (const float*)d_in[13];
    const float* g5 = (const float*)d_in[14];
    const float* b5 = (const float*)d_in[15];
    const float* fw1 = (const float*)d_in[16];
    const float* fb1 = (const float*)d_in[17];
    const float* g6 = (const float*)d_in[18];
    const float* b6 = (const float*)d_in[19];
    const float* fw2 = (const float*)d_in[20];
    const float* fb2 = (const float*)d_in[21];
    const float* g7 = (const float*)d_in[22];
    const float* b7 = (const float*)d_in[23];

    float *x0, *xcat;
    cudaGetSymbolAddress((void**)&x0, g_x0);
    cudaGetSymbolAddress((void**)&xcat, g_xcat);
    float* x1 = xcat;                  // ch 0..63
    float* x2 = xcat + 64 * NPTS;      // ch 64..127
    float* x3 = xcat + 128 * NPTS;     // ch 128..255
    float* x4 = xcat + 256 * NPTS;     // ch 256..511

    k_transpose<<<(BATCH * NPTS + 255) / 256, 256>>>(pts);
    run_edge(x0, 3,   3 * NPTS,  w1, g1, b1, x1, 64);
    run_edge(x1, 64,  CAT_BSTR,  w2, g2, b2, x2, 64);
    run_edge(x2, 64,  CAT_BSTR,  w3, g3, b3, x3, 128);
    run_edge(x3, 128, CAT_BSTR,  w4, g4, b4, x4, 256);
    k_conv5<<<dim3(NPTS / 128, 1024 / 128, BATCH), 256>>>(w5, g5, b5);
    k_pool<<<dim3(1024 / 256, BATCH), 256>>>();
    k_fc1<<<dim3(512 / 8, BATCH), 256>>>(fw1, fb1, g6, b6);
    k_fc2<<<dim3(256 / 8, BATCH), 256>>>(fw2, fb2, g7, b7, (float*)d_out);
}

// round 3
// speedup vs baseline: 1.6209x; 1.1680x over previous
#include <cuda_runtime.h>
#include <cfloat>
#include <cstddef>

#define NPTS 2048
#define BATCH 4
#define KNN 20

// ---------------- scratch (device globals; no allocation allowed) ----------
__device__ float g_x0[BATCH * 3 * NPTS];
// concat feature buffer: (B, 512, N). x1 @ ch 0, x2 @ 64, x3 @ 128, x4 @ 256
__device__ float g_xcat[(size_t)BATCH * 512 * NPTS];
__device__ float g_xx[BATCH * NPTS];
__device__ float g_D[(size_t)BATCH * NPTS * NPTS];       // 64 MB, reused per layer
__device__ int   g_knn[BATCH * NPTS * KNN];
__device__ float g_Y[BATCH * NPTS * 256];                // n-major, stride 256
__device__ float g_Z[BATCH * NPTS * 256];
__device__ float g_h5[(size_t)BATCH * NPTS * 1024];      // 32 MB
__device__ float g_f[BATCH * 2048];
__device__ float g_fc1[BATCH * 512];

__device__ __forceinline__ float lrelu(float v) { return v > 0.f ? v : 0.2f * v; }
#define BN_RSQ 0.99999500003749968750f  /* rsqrt(1+1e-5) */
#define CAT_BSTR (512 * NPTS)

// ---------------- transpose points (B,N,3) -> (B,3,N) ----------------------
__global__ void k_transpose(const float* __restrict__ pts) {
    int i = blockIdx.x * blockDim.x + threadIdx.x;
    if (i < BATCH * NPTS) {
        int b = i / NPTS, n = i % NPTS;
        #pragma unroll
        for (int c = 0; c < 3; c++)
            g_x0[(b * 3 + c) * NPTS + n] = pts[(b * NPTS + n) * 3 + c];
    }
}

// ---------------- row norms ------------------------------------------------
__global__ void k_xx(const float* __restrict__ feat, int C, int bstr) {
    int i = blockIdx.x * blockDim.x + threadIdx.x;
    if (i < BATCH * NPTS) {
        int b = i / NPTS, n = i % NPTS;
        const float* f = feat + (size_t)b * bstr + n;
        float s = 0.f;
        for (int c = 0; c < C; c++) { float v = f[(size_t)c * NPTS]; s = fmaf(v, v, s); }
        g_xx[i] = s;
    }
}

// ---------------- distance GEMM: D = 2 X^T X - xx_i - xx_j -----------------
// 128x128 tile, 8x8 per thread, K-step 8. grid (N/128, N/128, B), 256 thr.
__global__ void k_dist(const float* __restrict__ feat, int C, int bstr) {
    __shared__ float As[8][128];
    __shared__ float Bs[8][128];
    int b = blockIdx.z;
    int i0 = blockIdx.y * 128, j0 = blockIdx.x * 128;
    const float* fb = feat + (size_t)b * bstr;
    int tx = threadIdx.x & 15, ty = threadIdx.x >> 4;
    int lr = threadIdx.x & 31, lc = threadIdx.x >> 5;   // load: col-group, k-row
    float acc[8][8] = {};
    for (int c0 = 0; c0 < C; c0 += 8) {
        int c = c0 + lc;
        float4 av = {0.f, 0.f, 0.f, 0.f}, bv = {0.f, 0.f, 0.f, 0.f};
        if (c < C) {
            av = *(const float4*)&fb[(size_t)c * NPTS + i0 + lr * 4];
            bv = *(const float4*)&fb[(size_t)c * NPTS + j0 + lr * 4];
        }
        *(float4*)&As[lc][lr * 4] = av;
        *(float4*)&Bs[lc][lr * 4] = bv;
        __syncthreads();
        #pragma unroll
        for (int kk = 0; kk < 8; kk++) {
            float a[8], bb[8];
            *(float4*)&a[0] = *(const float4*)&As[kk][ty * 8];
            *(float4*)&a[4] = *(const float4*)&As[kk][ty * 8 + 4];
            *(float4*)&bb[0] = *(const float4*)&Bs[kk][tx * 8];
            *(float4*)&bb[4] = *(const float4*)&Bs[kk][tx * 8 + 4];
            #pragma unroll
            for (int r = 0; r < 8; r++)
                #pragma unroll
                for (int s = 0; s < 8; s++)
                    acc[r][s] = fmaf(a[r], bb[s], acc[r][s]);
        }
        __syncthreads();
    }
    float xj[8];
    #pragma unroll
    for (int s = 0; s < 8; s++) xj[s] = g_xx[b * NPTS + j0 + tx * 8 + s];
    #pragma unroll
    for (int r = 0; r < 8; r++) {
        int i = i0 + ty * 8 + r;
        float xi = g_xx[b * NPTS + i];
        float o[8];
        #pragma unroll
        for (int s = 0; s < 8; s++) o[s] = 2.f * acc[r][s] - xi - xj[s];
        float* dst = &g_D[((size_t)b * NPTS + i) * NPTS + j0 + tx * 8];
        *(float4*)&dst[0] = *(float4*)&o[0];
        *(float4*)&dst[4] = *(float4*)&o[4];
    }
}

// ---------------- top-K (K=20, largest, ties -> lower index) ---------------
// warp per row. Phase 1: per-lane top-2 -> exact conservative threshold Te
// (20th largest of the union of per-lane top-2 <= true 20th). Phase 2:
// rescan (L1-hot), insert only candidates >= Te into 20-deep sorted list
// (expected ~1-2 inserts/lane). Phase 3: exact 20-pop warp merge w/ index
// tie-break. grid (B*N/8), 256 threads.
__global__ void k_topk() {
    int warp = threadIdx.x >> 5, lane = threadIdx.x & 31;
    int row = blockIdx.x * 8 + warp;          // row = b*N + n
    const float* drow = g_D + (size_t)row * NPTS;

    // ---- phase 1: per-lane top-2 values (branchless) ----
    float v1 = -FLT_MAX, v2 = -FLT_MAX;
    #pragma unroll
    for (int t = 0; t < NPTS / 128; t++) {
        float4 q = *(const float4*)&drow[t * 128 + lane * 4];
        float mn1 = fminf(q.x, q.y), mx1 = fmaxf(q.x, q.y);
        float mn2 = fminf(q.z, q.w), mx2 = fmaxf(q.z, q.w);
        float a = fmaxf(mx1, mx2);                               // max of 4
        float bq = fmaxf(fminf(mx1, mx2), fmaxf(mn1, mn2));      // 2nd of 4
        float nv1 = fmaxf(v1, a);
        float nv2 = fmaxf(fminf(v1, a), fmaxf(v2, bq));
        v1 = nv1; v2 = nv2;
    }

    // ---- 20 value-pops over top-2 pairs -> Te (<= true 20th largest) ----
    float Te = -FLT_MAX;
    #pragma unroll 1
    for (int k = 0; k < KNN; k++) {
        float wv = v1;
        #pragma unroll
        for (int s = 16; s > 0; s >>= 1)
            wv = fmaxf(wv, __shfl_xor_sync(0xffffffffu, wv, s));
        unsigned m = __ballot_sync(0xffffffffu, v1 == wv);
        int leader = __ffs(m) - 1;
        if (lane == leader) { v1 = v2; v2 = -FLT_MAX; }
        Te = wv;
    }

    // ---- phase 2: filtered rescan into 20-deep sorted list ----
    float arr[KNN];
    int   ai[KNN];
    #pragma unroll
    for (int q = 0; q < KNN; q++) { arr[q] = -FLT_MAX; ai[q] = 0x7FFFFFFF; }
    #pragma unroll 2
    for (int t = 0; t < NPTS / 128; t++) {
        int jb = t * 128 + lane * 4;
        float4 v4 = *(const float4*)&drow[jb];
        float vv[4] = {v4.x, v4.y, v4.z, v4.w};
        #pragma unroll
        for (int m = 0; m < 4; m++) {
            float v = vv[m];
            if (v >= Te && v > arr[0]) {      // strict vs arr: earlier idx wins
                arr[0] = v; ai[0] = jb + m;
                #pragma unroll
                for (int q = 0; q < KNN - 1; q++) {
                    if (arr[q + 1] < arr[q]) {
                        float tv = arr[q]; arr[q] = arr[q + 1]; arr[q + 1] = tv;
                        int ti = ai[q]; ai[q] = ai[q + 1]; ai[q + 1] = ti;
                    }
                }
            }
        }
    }

    // ---- phase 3: exact 20 pops (value desc, index asc on ties) ----
    #pragma unroll 1
    for (int k = 0; k < KNN; k++) {
        float cv = arr[KNN - 1];
        int   ci = ai[KNN - 1];
        float wv = cv; int wi = ci;
        #pragma unroll
        for (int s = 16; s > 0; s >>= 1) {
            float ov = __shfl_xor_sync(0xffffffffu, wv, s);
            int   oi = __shfl_xor_sync(0xffffffffu, wi, s);
            if (ov > wv || (ov == wv && oi < wi)) { wv = ov; wi = oi; }
        }
        if (lane == 0) g_knn[(size_t)row * KNN + k] = wi;
        if (ci == wi) {                        // this lane's max was consumed
            #pragma unroll
            for (int q = KNN - 1; q > 0; q--) { arr[q] = arr[q - 1]; ai[q] = ai[q - 1]; }
            arr[0] = -FLT_MAX; ai[0] = 0x7FFFFFFF;
        }
    }
}

// ---------------- Y = W2 X, Z = (W1-W2) X ; stored n-major stride 256 ------
// grid (N/64, Cout/64, B), 256 threads
__global__ void k_yz(const float* __restrict__ feat, const float* __restrict__ W,
                     int C, int Cout, int bstr) {
    __shared__ float As[16][64];
    __shared__ float B1[16][64];
    __shared__ float B2[16][64];
    int b = blockIdx.z;
    int n0 = blockIdx.x * 64, o0 = blockIdx.y * 64;
    const float* fb = feat + (size_t)b * bstr;
    int tx = threadIdx.x & 15, ty = threadIdx.x >> 4;
    float aU[4][4] = {}, aY[4][4] = {};
    for (int c0 = 0; c0 < C; c0 += 16) {
        for (int e = threadIdx.x; e < 1024; e += 256) {
            int kk = e >> 6, nn = e & 63;
            int c = c0 + kk;
            As[kk][nn] = (c < C) ? fb[(size_t)c * NPTS + n0 + nn] : 0.f;
        }
        for (int e = threadIdx.x; e < 1024; e += 256) {
            int kk = e & 15, oo = e >> 4;
            int c = c0 + kk;
            float w1 = 0.f, w2 = 0.f;
            if (c < C) {
                const float* wr = W + (size_t)(o0 + oo) * (2 * C);
                w1 = wr[c]; w2 = wr[C + c];
            }
            B1[kk][oo] = w1; B2[kk][oo] = w2;
        }
        __syncthreads();
        #pragma unroll
        for (int kk = 0; kk < 16; kk++) {
            float4 a4 = *(const float4*)&As[kk][ty * 4];
            float4 b14 = *(const float4*)&B1[kk][tx * 4];
            float4 b24 = *(const float4*)&B2[kk][tx * 4];
            float av[4] = {a4.x, a4.y, a4.z, a4.w};
            float b1v[4] = {b14.x, b14.y, b14.z, b14.w};
            float b2v[4] = {b24.x, b24.y, b24.z, b24.w};
            #pragma unroll
            for (int r = 0; r < 4; r++)
                #pragma unroll
                for (int s = 0; s < 4; s++) {
                    aU[r][s] = fmaf(av[r], b1v[s], aU[r][s]);
                    aY[r][s] = fmaf(av[r], b2v[s], aY[r][s]);
                }
        }
        __syncthreads();
    }
    #pragma unroll
    for (int r = 0; r < 4; r++) {
        int n = n0 + ty * 4 + r;
        size_t base = ((size_t)b * NPTS + n) * 256 + o0 + tx * 4;
        float4 y, z;
        y.x = aY[r][0]; y.y = aY[r][1]; y.z = aY[r][2]; y.w = aY[r][3];
        z.x = aU[r][0] - y.x; z.y = aU[r][1] - y.y;
        z.z = aU[r][2] - y.z; z.w = aU[r][3] - y.w;
        *(float4*)&g_Y[base] = y;
        *(float4*)&g_Z[base] = z;
    }
}

// ---------------- gather-max + BN + lrelu -> out slice of g_xcat -----------
// grid (N/32, B), blockDim = Cout
__global__ void k_gather(float* __restrict__ out, const float* __restrict__ gam,
                         const float* __restrict__ bet, int Cout, int bstr) {
    __shared__ int   sidx[32 * KNN];
    __shared__ float sout[256 * 33];
    int b = blockIdx.y, n0 = blockIdx.x * 32;
    for (int e = threadIdx.x; e < 32 * KNN; e += blockDim.x)
        sidx[e] = g_knn[((size_t)b * NPTS + n0) * KNN + e];
    __syncthreads();
    int o = threadIdx.x;
    float sc = gam[o] * BN_RSQ, bi = bet[o];
    const float* Yb = g_Y + (size_t)b * NPTS * 256;
    const float* Zb = g_Z + (size_t)b * NPTS * 256;
    for (int nn = 0; nn < 32; nn++) {
        float m = -FLT_MAX;
        #pragma unroll
        for (int k = 0; k < KNN; k++) {
            int j = sidx[nn * KNN + k];
            m = fmaxf(m, Yb[(size_t)j * 256 + o]);
        }
        float v = Zb[(size_t)(n0 + nn) * 256 + o] + m;
        v = lrelu(fmaf(v, sc, bi));
        sout[o * 33 + nn] = v;
    }
    __syncthreads();
    float* ob = out + (size_t)b * bstr;
    for (int e = threadIdx.x; e < Cout * 32; e += blockDim.x) {
        int oo = e >> 5, nn = e & 31;
        ob[(size_t)oo * NPTS + n0 + nn] = sout[oo * 33 + nn];
    }
}

// ---------------- conv5 (512->1024) + BN + lrelu -> g_h5 (n-major) ---------
// 128x128 tile, 8x8/thread. grid (N/128, 1024/128, B), 256 threads
__global__ void k_conv5(const float* __restrict__ W5, const float* __restrict__ gam,
                        const float* __restrict__ bet) {
    __shared__ float As[8][128];
    __shared__ float Bs[8][128];
    int b = blockIdx.z;
    int n0 = blockIdx.x * 128, o0 = blockIdx.y * 128;
    int tx = threadIdx.x & 15, ty = threadIdx.x >> 4;
    int lr = threadIdx.x & 31, lc = threadIdx.x >> 5;
    int wo = threadIdx.x >> 1, wk = (threadIdx.x & 1) * 4;   // weight-load mapping
    const float* xb = g_xcat + (size_t)b * CAT_BSTR;
    float acc[8][8] = {};
    for (int c0 = 0; c0 < 512; c0 += 8) {
        float4 av = *(const float4*)&xb[(size_t)(c0 + lc) * NPTS + n0 + lr * 4];
        float4 wv = *(const float4*)&W5[(size_t)(o0 + wo) * 512 + c0 + wk];
        *(float4*)&As[lc][lr * 4] = av;
        Bs[wk + 0][wo] = wv.x;
        Bs[wk + 1][wo] = wv.y;
        Bs[wk + 2][wo] = wv.z;
        Bs[wk + 3][wo] = wv.w;
        __syncthreads();
        #pragma unroll
        for (int kk = 0; kk < 8; kk++) {
            float a[8], bb[8];
            *(float4*)&a[0] = *(const float4*)&As[kk][ty * 8];
            *(float4*)&a[4] = *(const float4*)&As[kk][ty * 8 + 4];
            *(float4*)&bb[0] = *(const float4*)&Bs[kk][tx * 8];
            *(float4*)&bb[4] = *(const float4*)&Bs[kk][tx * 8 + 4];
            #pragma unroll
            for (int r = 0; r < 8; r++)
                #pragma unroll
                for (int s = 0; s < 8; s++)
                    acc[r][s] = fmaf(a[r], bb[s], acc[r][s]);
        }
        __syncthreads();
    }
    float sc[8], bi[8];
    #pragma unroll
    for (int s = 0; s < 8; s++) {
        int o = o0 + tx * 8 + s;
        sc[s] = gam[o] * BN_RSQ; bi[s] = bet[o];
    }
    #pragma unroll
    for (int r = 0; r < 8; r++) {
        int n = n0 + ty * 8 + r;
        float o[8];
        #pragma unroll
        for (int s = 0; s < 8; s++) o[s] = lrelu(fmaf(acc[r][s], sc[s], bi[s]));
        float* dst = &g_h5[((size_t)b * NPTS + n) * 1024 + o0 + tx * 8];
        *(float4*)&dst[0] = *(float4*)&o[0];
        *(float4*)&dst[4] = *(float4*)&o[4];
    }
}

// ---------------- global max + mean pool -> g_f (B, 2048) ------------------
__global__ void k_pool() {
    int b = blockIdx.y;
    int o = blockIdx.x * 256 + threadIdx.x;
    const float* h = g_h5 + (size_t)b * NPTS * 1024;
    float mx = -FLT_MAX, sm = 0.f;
    #pragma unroll 8
    for (int n = 0; n < NPTS; n++) {
        float v = h[(size_t)n * 1024 + o];
        mx = fmaxf(mx, v);
        sm += v;
    }
    g_f[b * 2048 + o] = mx;
    g_f[b * 2048 + 1024 + o] = sm * (1.0f / NPTS);
}

// ---------------- fc1: 2048->512, BN + lrelu -------------------------------
__global__ void k_fc1(const float* __restrict__ fw, const float* __restrict__ fb,
                      const float* __restrict__ gam, const float* __restrict__ bet) {
    int b = blockIdx.y;
    int w = threadIdx.x >> 5, lane = threadIdx.x & 31;
    int o = blockIdx.x * 8 + w;
    const float* f = g_f + b * 2048;
    const float* wr = fw + (size_t)o * 2048;
    float acc = 0.f;
    for (int c = lane; c < 2048; c += 32) acc = fmaf(f[c], wr[c], acc);
    #pragma unroll
    for (int s = 16; s > 0; s >>= 1) acc += __shfl_xor_sync(0xffffffffu, acc, s);
    if (lane == 0) {
        float v = acc + fb[o];
        v = lrelu(fmaf(v, gam[o] * BN_RSQ, bet[o]));
        g_fc1[b * 512 + o] = v;
    }
}

// ---------------- fc2: 512->256, BN (no lrelu) -> d_out --------------------
__global__ void k_fc2(const float* __restrict__ fw, const float* __restrict__ fb,
                      const float* __restrict__ gam, const float* __restrict__ bet,
                      float* __restrict__ out) {
    int b = blockIdx.y;
    int w = threadIdx.x >> 5, lane = threadIdx.x & 31;
    int o = blockIdx.x * 8 + w;
    const float* f = g_fc1 + b * 512;
    const float* wr = fw + (size_t)o * 512;
    float acc = 0.f;
    for (int c = lane; c < 512; c += 32) acc = fmaf(f[c], wr[c], acc);
    #pragma unroll
    for (int s = 16; s > 0; s >>= 1) acc += __shfl_xor_sync(0xffffffffu, acc, s);
    if (lane == 0) {
        float v = acc + fb[o];
        out[b * 256 + o] = fmaf(v, gam[o] * BN_RSQ, bet[o]);
    }
}

// ---------------- driver ---------------------------------------------------
static void run_edge(const float* feat, int C, int bstr, const float* W,
                     const float* gam, const float* bet,
                     float* out, int Cout) {
    k_xx<<<(BATCH * NPTS + 255) / 256, 256>>>(feat, C, bstr);
    k_dist<<<dim3(NPTS / 128, NPTS / 128, BATCH), 256>>>(feat, C, bstr);
    k_topk<<<BATCH * NPTS / 8, 256>>>();
    k_yz<<<dim3(NPTS / 64, Cout / 64, BATCH), 256>>>(feat, W, C, Cout, bstr);
    k_gather<<<dim3(NPTS / 32, BATCH), Cout>>>(out, gam, bet, Cout, CAT_BSTR);
}

extern "C" void kernel_launch(void* const* d_in, const int* in_sizes, int n_in,
                              void* d_out, int out_size) {
    const float* pts = (const float*)d_in[0];
    const float* w1 = (const float*)d_in[1];
    const float* g1 = (const float*)d_in[2];
    const float* b1 = (const float*)d_in[3];
    const float* w2 = (const float*)d_in[4];
    const float* g2 = (const float*)d_in[5];
    const float* b2 = (const float*)d_in[6];
    const float* w3 = (const float*)d_in[7];
    const float* g3 = (const float*)d_in[8];
    const float* b3 = (const float*)d_in[9];
    const float* w4 = (const float*)d_in[10];
    const float* g4 = (const float*)d_in[11];
    const float* b4 = (const float*)d_in[12];
    const float* w5 = (const float*)d_in[13];
    const float* g5 = (const float*)d_in[14];
    const float* b5 = (const float*)d_in[15];
    const float* fw1 = (const float*)d_in[16];
    const float* fb1 = (const float*)d_in[17];
    const float* g6 = (const float*)d_in[18];
    const float* b6 = (const float*)d_in[19];
    const float* fw2 = (const float*)d_in[20];
    const float* fb2 = (const float*)d_in[21];
    const float* g7 = (const float*)d_in[22];
    const float* b7 = (const float*)d_in[23];

    float *x0, *xcat;
    cudaGetSymbolAddress((void**)&x0, g_x0);
    cudaGetSymbolAddress((void**)&xcat, g_xcat);
    float* x1 = xcat;                  // ch 0..63
    float* x2 = xcat + 64 * NPTS;      // ch 64..127
    float* x3 = xcat + 128 * NPTS;     // ch 128..255
    float* x4 = xcat + 256 * NPTS;     // ch 256..511

    k_transpose<<<(BATCH * NPTS + 255) / 256, 256>>>(pts);
    run_edge(x0, 3,   3 * NPTS,  w1, g1, b1, x1, 64);
    run_edge(x1, 64,  CAT_BSTR,  w2, g2, b2, x2, 64);
    run_edge(x2, 64,  CAT_BSTR,  w3, g3, b3, x3, 128);
    run_edge(x3, 128, CAT_BSTR,  w4, g4, b4, x4, 256);
    k_conv5<<<dim3(NPTS / 128, 1024 / 128, BATCH), 256>>>(w5, g5, b5);
    k_pool<<<dim3(1024 / 256, BATCH), 256>>>();
    k_fc1<<<dim3(512 / 8, BATCH), 256>>>(fw1, fb1, g6, b6);
    k_fc2<<<dim3(256 / 8, BATCH), 256>>>(fw2, fb2, g7, b7, (float*)d_out);
}